// round 10
// baseline (speedup 1.0000x reference)
#include <cuda_runtime.h>
#include <cstdint>

#define B_ 64
#define T_ 1024
#define F_ 128
#define U_ 256

// Scratch for h = inputs @ R, layout [B, T, U]; +U_ pad so the t+1 prefetch
// on the last step never reads out of bounds.
__device__ float g_h[(size_t)B_ * T_ * U_ + U_];

// ---------------- helpers ----------------

__device__ __forceinline__ unsigned smem_u32(const void* p) {
    return (unsigned)__cvta_generic_to_shared(p);
}
__device__ __forceinline__ unsigned long long dup2(float s) {
    unsigned long long r;
    asm("mov.b64 %0, {%1, %1};" : "=l"(r) : "r"(__float_as_uint(s)));
    return r;
}
__device__ __forceinline__ unsigned long long pk2(float lo, float hi) {
    unsigned long long r;
    asm("mov.b64 %0, {%1, %2};" : "=l"(r)
        : "r"(__float_as_uint(lo)), "r"(__float_as_uint(hi)));
    return r;
}
__device__ __forceinline__ unsigned long long ffma2(unsigned long long a, unsigned long long b,
                                                    unsigned long long c) {
    unsigned long long d;
    asm("fma.rn.f32x2 %0, %1, %2, %3;" : "=l"(d) : "l"(a), "l"(b), "l"(c));
    return d;
}
__device__ __forceinline__ unsigned long long fadd2(unsigned long long a, unsigned long long b) {
    unsigned long long d;
    asm("add.rn.f32x2 %0, %1, %2;" : "=l"(d) : "l"(a), "l"(b));
    return d;
}
__device__ __forceinline__ float2 unpk(unsigned long long v) {
    unsigned lo, hi;
    asm("mov.b64 {%0, %1}, %2;" : "=r"(lo), "=r"(hi) : "l"(v));
    return make_float2(__uint_as_float(lo), __uint_as_float(hi));
}
__device__ __forceinline__ unsigned mapa_u32(unsigned addr, unsigned rank) {
    unsigned r;
    asm("mapa.shared::cluster.u32 %0, %1, %2;" : "=r"(r) : "r"(addr), "r"(rank));
    return r;
}
// weak 8B store into peer smem
__device__ __forceinline__ void st_remote_u64(unsigned addr, unsigned long long v) {
    asm volatile("st.shared::cluster.u64 [%0], %1;" :: "r"(addr), "l"(v) : "memory");
}
// release 4B store into peer smem (publishes all prior stores of this thread)
__device__ __forceinline__ void st_remote_release_u32(unsigned addr, unsigned v) {
    asm volatile("st.release.cluster.shared::cluster.u32 [%0], %1;"
                 :: "r"(addr), "r"(v) : "memory");
}
// acquire-poll a local-smem flag until it equals `want`
__device__ __forceinline__ void poll_flag(unsigned addr, unsigned want) {
    unsigned f;
    do {
        asm volatile("ld.acquire.cluster.shared::cta.u32 %0, [%1];"
                     : "=r"(f) : "r"(addr) : "memory");
    } while (f != want);
}
__device__ __forceinline__ void cluster_sync_() {
    asm volatile("barrier.cluster.arrive.aligned;" ::: "memory");
    asm volatile("barrier.cluster.wait.aligned;" ::: "memory");
}
// accurate tanh: |err| ~1e-6 rel, overflow-free
__device__ __forceinline__ float fast_tanh(float x) {
    float ax = fabsf(x) * -2.885390081777927f;  // -2*log2(e)
    float e;
    asm("ex2.approx.f32 %0, %1;" : "=f"(e) : "f"(ax));
    float num = 1.0f - e;
    float den = 1.0f + e;
    float r;
    asm("rcp.approx.f32 %0, %1;" : "=f"(r) : "f"(den));
    return copysignf(num * r, x);
}

// ---------------- phase 1: h = inputs @ R ----------------
__global__ void __launch_bounds__(256, 1)
proj_kernel(const float* __restrict__ inp, const float* __restrict__ R)
{
    __shared__ __align__(16) unsigned long long in_dupT[128 * 18];  // [f][r] pad 18
    __shared__ __align__(16) unsigned long long partsm[128 * 17];   // pad 17

    const int tid = threadIdx.x;
    const int up = tid & 127;
    const int fh = tid >> 7;

    unsigned long long w[64];
    const unsigned long long* R64 = (const unsigned long long*)R;
#pragma unroll
    for (int j = 0; j < 64; j++)
        w[j] = R64[(64 * fh + j) * 128 + up];

    const int ntiles = (B_ * T_) / 16;
    for (int tile = blockIdx.x; tile < ntiles; tile += gridDim.x) {
        const int row0 = tile * 16;
        __syncthreads();
#pragma unroll
        for (int e = 0; e < 8; e++) {
            int idx = e * 256 + tid;
            int r = idx >> 7, f = idx & 127;
            float v = inp[(size_t)(row0 + r) * F_ + f];
            in_dupT[f * 18 + r] = dup2(v);
        }
        __syncthreads();

        unsigned long long acc[16];
#pragma unroll
        for (int r = 0; r < 16; r++) acc[r] = 0ull;

#pragma unroll
        for (int j = 0; j < 64; j++) {
            const int f = 64 * fh + j;
            const ulonglong2* col = (const ulonglong2*)&in_dupT[f * 18];
#pragma unroll
            for (int rr = 0; rr < 8; rr++) {
                ulonglong2 v = col[rr];
                acc[2 * rr]     = ffma2(v.x, w[j], acc[2 * rr]);
                acc[2 * rr + 1] = ffma2(v.y, w[j], acc[2 * rr + 1]);
            }
        }
        if (fh) {
#pragma unroll
            for (int r = 0; r < 16; r++) partsm[up * 17 + r] = acc[r];
        }
        __syncthreads();
        if (!fh) {
#pragma unroll
            for (int r = 0; r < 16; r++) {
                unsigned long long tot = fadd2(acc[r], partsm[up * 17 + r]);
                float2 o = unpk(tot);
                *(float2*)&g_h[(size_t)(row0 + r) * U_ + 2 * up] = o;
            }
        }
    }
}

// ---------------- phase 2: the recurrence (U-split, data-flow exchange) ----
// 2-CTA cluster per batch. CTA rank r produces u in [128r, 128r+128) with the
// FULL K=256 weights register-resident (k-paired f32x2). Exchange: right after
// tanh, sender threads push their fresh state pair straight into the peer's
// s_peer buffer (weak st.shared::cluster.u64) and publish it with a per-slot
// release flag = t. Next step, every thread acquire-polls one designated flag
// (== t-1), then the step's single __syncthreads makes all slots visible
// CTA-wide. No mbarrier, no bulk copy, no fence, one barrier per step.
__global__ void __launch_bounds__(256, 1) __cluster_dims__(2, 1, 1)
rnn_kernel(const float* __restrict__ W, const float* __restrict__ bias,
           const float* __restrict__ x0, float* __restrict__ out)
{
    __shared__ __align__(16) unsigned long long s_loc[2][64];   // own half (u64 pairs)
    __shared__ __align__(16) unsigned long long s_peer[2][64];  // peer half (remote-written)
    __shared__ __align__(16) unsigned s_flag[2][64];            // per-slot step flags

    const int tid = threadIdx.x;
    const int u  = tid >> 1;   // local u index 0..127
    const int kh = tid & 1;    // k sub-half selector
    unsigned rank;
    asm("mov.u32 %0, %%cluster_ctarank;" : "=r"(rank));
    const int b = blockIdx.x >> 1;
    const int gu    = 128 * (int)rank + u;
    const int lbase = 128 * (int)rank;
    const int pbase = 128 * ((int)rank ^ 1);

    // weights: wl[m] = {W[lbase+64kh+2m][gu], W[lbase+64kh+2m+1][gu]}, m=0..31
    unsigned long long wl[32], wp[32];
#pragma unroll
    for (int m = 0; m < 32; m++) {
        int kl = lbase + 64 * kh + 2 * m;
        wl[m] = pk2(W[(size_t)kl * U_ + gu], W[(size_t)(kl + 1) * U_ + gu]);
        int kp = pbase + 64 * kh + 2 * m;
        wp[m] = pk2(W[(size_t)kp * U_ + gu], W[(size_t)(kp + 1) * U_ + gu]);
    }

    if (tid < 64) {
        s_loc[1][tid]  = pk2(x0[lbase + 2 * tid], x0[lbase + 2 * tid + 1]);
        s_peer[1][tid] = pk2(x0[pbase + 2 * tid], x0[pbase + 2 * tid + 1]);
    }
    if (tid < 128) s_flag[tid >> 6][tid & 63] = 0xFFFFFFFFu;  // never a valid t
    __syncthreads();
    cluster_sync_();  // buffers + flags initialized cluster-wide before traffic

    const unsigned peer = rank ^ 1u;
    const int slot = u >> 1;  // u-pair slot for sender threads
    // my state lands in the PEER's s_peer buffer / flags
    const unsigned r_data[2] = {
        mapa_u32(smem_u32(&s_peer[0][0]), peer) + (unsigned)slot * 8u,
        mapa_u32(smem_u32(&s_peer[1][0]), peer) + (unsigned)slot * 8u };
    const unsigned r_flag[2] = {
        mapa_u32(smem_u32(&s_flag[0][0]), peer) + (unsigned)slot * 4u,
        mapa_u32(smem_u32(&s_flag[1][0]), peer) + (unsigned)slot * 4u };
    // designated poll address (4 threads per slot, broadcast LDS)
    const unsigned l_flag[2] = {
        smem_u32(&s_flag[0][tid & 63]), smem_u32(&s_flag[1][tid & 63]) };

    const float bias_u = bias[gu];
    const float* hptr = &g_h[((size_t)b * T_) * U_ + gu];
    float hcur = hptr[0];

    const int role = tid & 3;  // 0: local store + STG;  1: remote send

    for (int t = 0; t < T_; t++) {
        const int prev = (t + 1) & 1;
        const int cur  = t & 1;

        // wait for the peer half of state_{t-1} (flag value == t-1)
        if (t > 0) poll_flag(l_flag[prev], (unsigned)(t - 1));
        __syncthreads();  // publishes s_loc[prev] writes + all polled slots

        float hnext = hptr[(size_t)(t + 1) * U_];  // pad makes last read safe

        // ---- local K-half ----
        unsigned long long a0 = 0ull, a1 = 0ull;
        const ulonglong2* sl = (const ulonglong2*)&s_loc[prev][32 * kh];
#pragma unroll
        for (int j = 0; j < 16; j++) {
            ulonglong2 v = sl[j];
            a0 = ffma2(v.x, wl[2 * j],     a0);
            a1 = ffma2(v.y, wl[2 * j + 1], a1);
        }
        // ---- peer K-half ----
        const ulonglong2* sp = (const ulonglong2*)&s_peer[prev][32 * kh];
#pragma unroll
        for (int j = 0; j < 16; j++) {
            ulonglong2 v = sp[j];
            a0 = ffma2(v.x, wp[2 * j],     a0);
            a1 = ffma2(v.y, wp[2 * j + 1], a1);
        }

        // ---- reduce kh-partials + activation ----
        float2 aa = unpk(fadd2(a0, a1));
        float s = aa.x + aa.y;
        s += __shfl_xor_sync(0xffffffffu, s, 1);
        float st = fast_tanh(s + hcur + bias_u);
        hcur = hnext;

        // gather the u+1 partner value (2 lanes over), then store/send pairs
        float stn = __shfl_down_sync(0xffffffffu, st, 2);
        if (role == 0) {            // kh=0, even u: local state + output
            unsigned long long pkv = pk2(st, stn);
            s_loc[cur][slot] = pkv;
            *(float2*)&out[((size_t)t * B_ + b) * U_ + gu] = make_float2(st, stn);
        } else if (role == 1 && t < T_ - 1) {  // kh=1, even u: ship to peer
            unsigned long long pkv = pk2(st, stn);
            st_remote_u64(r_data[cur], pkv);
            st_remote_release_u32(r_flag[cur], (unsigned)t);
        }
        // no trailing barrier: next iteration's poll + __syncthreads cover it
    }
    cluster_sync_();  // keep both CTAs alive until all remote traffic lands
}

// ---------------- launch ----------------

extern "C" void kernel_launch(void* const* d_in, const int* in_sizes, int n_in,
                              void* d_out, int out_size)
{
    (void)in_sizes; (void)n_in; (void)out_size;
    const float* inputs = (const float*)d_in[0];  // [B,T,F]
    const float* R      = (const float*)d_in[1];  // [F,U]
    const float* W      = (const float*)d_in[2];  // [U,U]
    const float* bias   = (const float*)d_in[3];  // [U]
    const float* x0     = (const float*)d_in[4];  // [U]
    float* out = (float*)d_out;                   // [T,B,U]

    proj_kernel<<<304, 256>>>(inputs, R);
    rnn_kernel<<<2 * B_, 256>>>(W, bias, x0, out);
}

// round 13
// speedup vs baseline: 2.7558x; 2.7558x over previous
#include <cuda_runtime.h>
#include <cstdint>

#define B_ 64
#define T_ 1024
#define F_ 128
#define U_ 256

// Scratch for h = inputs @ R, layout [B, T, U]; +U_ pad so the t+1 prefetch
// on the last step never reads out of bounds.
__device__ float g_h[(size_t)B_ * T_ * U_ + U_];

// ---------------- helpers ----------------

__device__ __forceinline__ unsigned smem_u32(const void* p) {
    return (unsigned)__cvta_generic_to_shared(p);
}
__device__ __forceinline__ unsigned long long dup2(float s) {
    unsigned long long r;
    asm("mov.b64 %0, {%1, %1};" : "=l"(r) : "r"(__float_as_uint(s)));
    return r;
}
__device__ __forceinline__ unsigned long long pk2(float lo, float hi) {
    unsigned long long r;
    asm("mov.b64 %0, {%1, %2};" : "=l"(r)
        : "r"(__float_as_uint(lo)), "r"(__float_as_uint(hi)));
    return r;
}
__device__ __forceinline__ unsigned long long ffma2(unsigned long long a, unsigned long long b,
                                                    unsigned long long c) {
    unsigned long long d;
    asm("fma.rn.f32x2 %0, %1, %2, %3;" : "=l"(d) : "l"(a), "l"(b), "l"(c));
    return d;
}
__device__ __forceinline__ unsigned long long fadd2(unsigned long long a, unsigned long long b) {
    unsigned long long d;
    asm("add.rn.f32x2 %0, %1, %2;" : "=l"(d) : "l"(a), "l"(b));
    return d;
}
__device__ __forceinline__ float2 unpk(unsigned long long v) {
    unsigned lo, hi;
    asm("mov.b64 {%0, %1}, %2;" : "=r"(lo), "=r"(hi) : "l"(v));
    return make_float2(__uint_as_float(lo), __uint_as_float(hi));
}
__device__ __forceinline__ unsigned mapa_u32(unsigned addr, unsigned rank) {
    unsigned r;
    asm("mapa.shared::cluster.u32 %0, %1, %2;" : "=r"(r) : "r"(addr), "r"(rank));
    return r;
}
__device__ __forceinline__ void mbar_init(unsigned addr, unsigned cnt) {
    asm volatile("mbarrier.init.shared.b64 [%0], %1;" :: "r"(addr), "r"(cnt) : "memory");
}
__device__ __forceinline__ void mbar_expect_tx(unsigned addr, unsigned bytes) {
    asm volatile("mbarrier.arrive.expect_tx.shared::cta.b64 _, [%0], %1;"
                 :: "r"(addr), "r"(bytes) : "memory");
}
__device__ __forceinline__ void mbar_wait(unsigned addr, unsigned parity) {
    asm volatile(
        "{\n\t"
        ".reg .pred P;\n"
        "WAIT%=:\n\t"
        "mbarrier.try_wait.parity.acquire.cluster.shared::cta.b64 P, [%0], %1, 0x989680;\n\t"
        "@!P bra WAIT%=;\n\t"
        "}"
        :: "r"(addr), "r"(parity) : "memory");
}
// 4B remote smem store; data lands in the peer CTA and credits 4 bytes of tx
// on the mbarrier co-located in that SAME peer CTA.
__device__ __forceinline__ void st_async_u32(unsigned r_addr, float v, unsigned r_bar) {
    asm volatile(
        "st.async.shared::cluster.mbarrier::complete_tx::bytes.b32 [%0], %1, [%2];"
        :: "r"(r_addr), "r"(__float_as_uint(v)), "r"(r_bar) : "memory");
}
__device__ __forceinline__ void cluster_sync_() {
    asm volatile("barrier.cluster.arrive.aligned;" ::: "memory");
    asm volatile("barrier.cluster.wait.aligned;" ::: "memory");
}
// accurate tanh: |err| ~1e-6 rel, overflow-free
__device__ __forceinline__ float fast_tanh(float x) {
    float ax = fabsf(x) * -2.885390081777927f;  // -2*log2(e)
    float e;
    asm("ex2.approx.f32 %0, %1;" : "=f"(e) : "f"(ax));
    float num = 1.0f - e;
    float den = 1.0f + e;
    float r;
    asm("rcp.approx.f32 %0, %1;" : "=f"(r) : "f"(den));
    return copysignf(num * r, x);
}

// ---------------- phase 1: h = inputs @ R ----------------
__global__ void __launch_bounds__(256, 1)
proj_kernel(const float* __restrict__ inp, const float* __restrict__ R)
{
    __shared__ __align__(16) unsigned long long in_dupT[128 * 18];  // [f][r] pad 18
    __shared__ __align__(16) unsigned long long partsm[128 * 17];   // pad 17

    const int tid = threadIdx.x;
    const int up = tid & 127;
    const int fh = tid >> 7;

    unsigned long long w[64];
    const unsigned long long* R64 = (const unsigned long long*)R;
#pragma unroll
    for (int j = 0; j < 64; j++)
        w[j] = R64[(64 * fh + j) * 128 + up];

    const int ntiles = (B_ * T_) / 16;
    for (int tile = blockIdx.x; tile < ntiles; tile += gridDim.x) {
        const int row0 = tile * 16;
        __syncthreads();
#pragma unroll
        for (int e = 0; e < 8; e++) {
            int idx = e * 256 + tid;
            int r = idx >> 7, f = idx & 127;
            float v = inp[(size_t)(row0 + r) * F_ + f];
            in_dupT[f * 18 + r] = dup2(v);
        }
        __syncthreads();

        unsigned long long acc[16];
#pragma unroll
        for (int r = 0; r < 16; r++) acc[r] = 0ull;

#pragma unroll
        for (int j = 0; j < 64; j++) {
            const int f = 64 * fh + j;
            const ulonglong2* col = (const ulonglong2*)&in_dupT[f * 18];
#pragma unroll
            for (int rr = 0; rr < 8; rr++) {
                ulonglong2 v = col[rr];
                acc[2 * rr]     = ffma2(v.x, w[j], acc[2 * rr]);
                acc[2 * rr + 1] = ffma2(v.y, w[j], acc[2 * rr + 1]);
            }
        }
        if (fh) {
#pragma unroll
            for (int r = 0; r < 16; r++) partsm[up * 17 + r] = acc[r];
        }
        __syncthreads();
        if (!fh) {
#pragma unroll
            for (int r = 0; r < 16; r++) {
                unsigned long long tot = fadd2(acc[r], partsm[up * 17 + r]);
                float2 o = unpk(tot);
                *(float2*)&g_h[(size_t)(row0 + r) * U_ + 2 * up] = o;
            }
        }
    }
}

// ---------------- phase 2: the recurrence (U-split, st.async exchange) -----
// 2-CTA cluster per batch. CTA rank r produces u in [128r, 128r+128) with the
// FULL K=256 weights register-resident (k-paired f32x2). Exchange: right after
// tanh, each kh=1 thread fires its fresh scalar state at the peer's s_peer
// buffer with st.async (128 x 4B = 512B), all crediting the peer's
// tx-mbarrier. Consumer posts expect_tx(512) at step top, runs its local-half
// FMAs, then try_wait (cheap HW wakeup) before the peer-half FMAs. One
// __syncthreads per step; double-buffered; parity/backpressure identical to
// the proven bulk-copy scheme.
__global__ void __launch_bounds__(256, 1) __cluster_dims__(2, 1, 1)
rnn_kernel(const float* __restrict__ W, const float* __restrict__ bias,
           const float* __restrict__ x0, float* __restrict__ out)
{
    __shared__ __align__(16) float s_loc[2][128];   // own half (local writes)
    __shared__ __align__(16) float s_peer[2][128];  // peer half (st.async writes)
    __shared__ __align__(8)  unsigned long long mbar[2];

    const int tid = threadIdx.x;
    const int u  = tid >> 1;   // local u index 0..127
    const int kh = tid & 1;    // k sub-half selector
    unsigned rank;
    asm("mov.u32 %0, %%cluster_ctarank;" : "=r"(rank));
    const int b = blockIdx.x >> 1;
    const int gu    = 128 * (int)rank + u;
    const int lbase = 128 * (int)rank;
    const int pbase = 128 * ((int)rank ^ 1);

    // weights: wl[m] = {W[lbase+64kh+2m][gu], W[lbase+64kh+2m+1][gu]}, m=0..31
    unsigned long long wl[32], wp[32];
#pragma unroll
    for (int m = 0; m < 32; m++) {
        int kl = lbase + 64 * kh + 2 * m;
        wl[m] = pk2(W[(size_t)kl * U_ + gu], W[(size_t)(kl + 1) * U_ + gu]);
        int kp = pbase + 64 * kh + 2 * m;
        wp[m] = pk2(W[(size_t)kp * U_ + gu], W[(size_t)(kp + 1) * U_ + gu]);
    }

    if (tid < 128) {
        s_loc[1][tid]  = x0[lbase + tid];
        s_peer[1][tid] = x0[pbase + tid];
    }
    if (tid == 0) {
        mbar_init(smem_u32(&mbar[0]), 1);
        mbar_init(smem_u32(&mbar[1]), 1);
    }
    __syncthreads();
    cluster_sync_();  // mbarriers + x0 visible cluster-wide before any traffic

    const unsigned peer = rank ^ 1u;
    // my scalar state[u] lands at the PEER's s_peer[buf][u]; tx credited on the
    // mbarrier in the SAME (peer) CTA.
    const unsigned r_data[2] = {
        mapa_u32(smem_u32(&s_peer[0][0]), peer) + (unsigned)u * 4u,
        mapa_u32(smem_u32(&s_peer[1][0]), peer) + (unsigned)u * 4u };
    const unsigned r_bar[2] = {
        mapa_u32(smem_u32(&mbar[0]), peer),
        mapa_u32(smem_u32(&mbar[1]), peer) };
    const unsigned l_bar[2] = { smem_u32(&mbar[0]), smem_u32(&mbar[1]) };

    const float bias_u = bias[gu];
    const float* hptr = &g_h[((size_t)b * T_) * U_ + gu];
    float hcur = hptr[0];

    for (int t = 0; t < T_; t++) {
        const int prev = (t + 1) & 1;   // buffer holding state_{t-1}
        const int cur  = t & 1;         // buffer receiving state_t

        float hnext = hptr[(size_t)(t + 1) * U_];  // pad makes last read safe

        // post expected bytes for this step's incoming peer half
        if (t > 0 && tid == 0) mbar_expect_tx(l_bar[prev], 512u);

        // ---- local K-half (own state, already in smem) ----
        unsigned long long a0 = 0ull, a1 = 0ull;
        const ulonglong2* sl = (const ulonglong2*)&s_loc[prev][64 * kh];
#pragma unroll
        for (int j = 0; j < 16; j++) {
            ulonglong2 v = sl[j];                 // 4 consecutive k-values
            a0 = ffma2(v.x, wl[2 * j],     a0);
            a1 = ffma2(v.y, wl[2 * j + 1], a1);
        }

        // ---- wait for the peer half (st.async'd during peer's step t-1) ----
        if (t > 0) mbar_wait(l_bar[prev], ((t - 1) >> 1) & 1);

        const ulonglong2* sp = (const ulonglong2*)&s_peer[prev][64 * kh];
#pragma unroll
        for (int j = 0; j < 16; j++) {
            ulonglong2 v = sp[j];
            a0 = ffma2(v.x, wp[2 * j],     a0);
            a1 = ffma2(v.y, wp[2 * j + 1], a1);
        }

        // ---- reduce the 2 kh-partials + activation ----
        float2 aa = unpk(fadd2(a0, a1));
        float s = aa.x + aa.y;
        s += __shfl_xor_sync(0xffffffffu, s, 1);
        float st = fast_tanh(s + hcur + bias_u);
        hcur = hnext;

        // ---- epilogue: fire remote scalar FIRST (starts DSMEM flight early),
        //      then local state + output stores ----
        if (kh) {
            if (t < T_ - 1) st_async_u32(r_data[cur], st, r_bar[cur]);
        } else {
            s_loc[cur][u] = st;
            out[((size_t)t * B_ + b) * U_ + gu] = st;
        }

        __syncthreads();  // s_loc[cur] visible CTA-wide for next step
    }
    cluster_sync_();  // keep both CTAs alive until all remote traffic lands
}

// ---------------- launch ----------------

extern "C" void kernel_launch(void* const* d_in, const int* in_sizes, int n_in,
                              void* d_out, int out_size)
{
    (void)in_sizes; (void)n_in; (void)out_size;
    const float* inputs = (const float*)d_in[0];  // [B,T,F]
    const float* R      = (const float*)d_in[1];  // [F,U]
    const float* W      = (const float*)d_in[2];  // [U,U]
    const float* bias   = (const float*)d_in[3];  // [U]
    const float* x0     = (const float*)d_in[4];  // [U]
    float* out = (float*)d_out;                   // [T,B,U]

    proj_kernel<<<304, 256>>>(inputs, R);
    rnn_kernel<<<2 * B_, 256>>>(W, bias, x0, out);
}